// round 1
// baseline (speedup 1.0000x reference)
#include <cuda_runtime.h>
#include <math.h>

#define B_      2
#define SEQ     1024
#define DIM_    1024
#define HEADS_  16
#define DH_     64
#define MLP_    4096
#define ROWS    (B_*SEQ)          // 2048
#define SCALE_  0.125f            // 64^-0.5
#define DEPTH_  2

// ---------------- scratch (device globals: allocation-guard-safe) -------------
__device__ float g_h   [ROWS*DIM_];        // 8 MB
__device__ float g_qkv [ROWS*3*DIM_];      // 24 MB
__device__ float g_q2  [ROWS*DIM_];
__device__ float g_k2  [ROWS*DIM_];
__device__ float g_v2  [ROWS*DIM_];
__device__ float g_o   [ROWS*DIM_];
__device__ float g_mlp [ROWS*MLP_];        // 32 MB
__device__ float g_s   [B_*HEADS_*SEQ*SEQ];// 128 MB scores

// ---------------- layernorm: one block per row ------------------------------
__global__ __launch_bounds__(256) void layernorm_k(
    const float* __restrict__ x, const float* __restrict__ g,
    const float* __restrict__ b, float* __restrict__ out)
{
    __shared__ float red[18];
    const int row = blockIdx.x;
    const int t   = threadIdx.x;
    const float4 v = ((const float4*)(x + (size_t)row*DIM_))[t];
    float s  = v.x + v.y + v.z + v.w;
    float sq = v.x*v.x + v.y*v.y + v.z*v.z + v.w*v.w;
    #pragma unroll
    for (int o = 16; o > 0; o >>= 1) {
        s  += __shfl_down_sync(0xffffffffu, s,  o);
        sq += __shfl_down_sync(0xffffffffu, sq, o);
    }
    if ((t & 31) == 0) { red[t >> 5] = s; red[8 + (t >> 5)] = sq; }
    __syncthreads();
    if (t < 32) {
        float a = (t < 8) ? red[t]     : 0.f;
        float c = (t < 8) ? red[8 + t] : 0.f;
        #pragma unroll
        for (int o = 4; o > 0; o >>= 1) {
            a += __shfl_down_sync(0xffffffffu, a, o);
            c += __shfl_down_sync(0xffffffffu, c, o);
        }
        if (t == 0) { red[16] = a; red[17] = c; }
    }
    __syncthreads();
    const float mu   = red[16] * (1.f / DIM_);
    const float var  = red[17] * (1.f / DIM_) - mu * mu;
    const float rstd = rsqrtf(var + 1e-5f);
    const float4 gv = ((const float4*)g)[t];
    const float4 bv = ((const float4*)b)[t];
    float4 o4;
    o4.x = (v.x - mu) * rstd * gv.x + bv.x;
    o4.y = (v.y - mu) * rstd * gv.y + bv.y;
    o4.z = (v.z - mu) * rstd * gv.z + bv.z;
    o4.w = (v.w - mu) * rstd * gv.w + bv.w;
    ((float4*)(out + (size_t)row*DIM_))[t] = o4;
}

// ---------------- SGEMM 128x128x8, 256 thr, 8x8 micro-tile -------------------
// C[M,N] = act(A[M,K] @ B[K,N] + bias) + res.   All dims % (128,128,8) == 0.
// act: 0 = none, 1 = exact GELU (x * Phi(x)).
__global__ __launch_bounds__(256) void sgemm_k(
    const float* __restrict__ A, const float* __restrict__ B,
    const float* __restrict__ bias, const float* __restrict__ res,
    float* __restrict__ C, int M, int N, int K, int act)
{
    __shared__ float As[8][128];
    __shared__ float Bs[8][128];
    const int tid = threadIdx.x;
    const int bm  = blockIdx.y, bn = blockIdx.x;
    const int tx  = tid & 15, ty = tid >> 4;

    const int a_row = tid >> 1;          // 0..127
    const int a_col = (tid & 1) * 4;     // 0 or 4
    const int b_row = tid >> 5;          // 0..7
    const int b_col = (tid & 31) * 4;    // 0..124
    const float* Ap = A + (size_t)(bm*128 + a_row) * K + a_col;
    const float* Bp = B + (size_t)b_row * N + bn*128 + b_col;

    float acc[8][8];
    #pragma unroll
    for (int i = 0; i < 8; i++)
        #pragma unroll
        for (int j = 0; j < 8; j++) acc[i][j] = 0.f;

    for (int kk = 0; kk < K; kk += 8) {
        const float4 av = *(const float4*)(Ap + kk);
        As[a_col + 0][a_row] = av.x;
        As[a_col + 1][a_row] = av.y;
        As[a_col + 2][a_row] = av.z;
        As[a_col + 3][a_row] = av.w;
        *(float4*)&Bs[b_row][b_col] = *(const float4*)(Bp + (size_t)kk * N);
        __syncthreads();
        #pragma unroll
        for (int k = 0; k < 8; k++) {
            float ar[8], br[8];
            const float4 a0 = *(const float4*)&As[k][ty*8];
            const float4 a1 = *(const float4*)&As[k][ty*8 + 4];
            ar[0]=a0.x; ar[1]=a0.y; ar[2]=a0.z; ar[3]=a0.w;
            ar[4]=a1.x; ar[5]=a1.y; ar[6]=a1.z; ar[7]=a1.w;
            const float4 b0 = *(const float4*)&Bs[k][tx*8];
            const float4 b1 = *(const float4*)&Bs[k][tx*8 + 4];
            br[0]=b0.x; br[1]=b0.y; br[2]=b0.z; br[3]=b0.w;
            br[4]=b1.x; br[5]=b1.y; br[6]=b1.z; br[7]=b1.w;
            #pragma unroll
            for (int i = 0; i < 8; i++)
                #pragma unroll
                for (int j = 0; j < 8; j++)
                    acc[i][j] = fmaf(ar[i], br[j], acc[i][j]);
        }
        __syncthreads();
    }

    float bj[8];
    #pragma unroll
    for (int j = 0; j < 8; j++)
        bj[j] = bias ? bias[bn*128 + tx*8 + j] : 0.f;

    #pragma unroll
    for (int i = 0; i < 8; i++) {
        const size_t row = (size_t)(bm*128 + ty*8 + i);
        #pragma unroll
        for (int j = 0; j < 8; j++) {
            const size_t idx = row * N + bn*128 + tx*8 + j;
            float v = acc[i][j] + bj[j];
            if (act == 1) v = v * normcdff(v);     // exact GELU
            if (res) v += res[idx];
            C[idx] = v;
        }
    }
}

// ---------------- attention: S = scale * Q K^T (per batch-head) --------------
// Q rows stride ldq (head h at column offset h*DH_ already folded into base ptr math)
__global__ __launch_bounds__(256) void attn_qk_k(
    const float* __restrict__ Q, int ldq,
    const float* __restrict__ Kp, int ldk,
    float* __restrict__ S)
{
    const int bh = blockIdx.z, b = bh >> 4, h = bh & 15;
    const int qt = blockIdx.y * 64, kt = blockIdx.x * 64;
    const float* qb = Q  + (size_t)(b*SEQ + qt) * ldq + h*DH_;
    const float* kb = Kp + (size_t)(b*SEQ + kt) * ldk + h*DH_;
    float* sb = g_s + (size_t)bh * SEQ * SEQ;   // ignore S param; use global directly
    (void)S;

    __shared__ float Qs[64][65];   // [d][n]
    __shared__ float Ks[64][65];   // [d][m]
    const int tid = threadIdx.x;
    for (int i = tid; i < 64*16; i += 256) {
        const int r = i >> 4, c4 = (i & 15) * 4;
        const float4 v = *(const float4*)(qb + (size_t)r*ldq + c4);
        Qs[c4+0][r]=v.x; Qs[c4+1][r]=v.y; Qs[c4+2][r]=v.z; Qs[c4+3][r]=v.w;
        const float4 w = *(const float4*)(kb + (size_t)r*ldk + c4);
        Ks[c4+0][r]=w.x; Ks[c4+1][r]=w.y; Ks[c4+2][r]=w.z; Ks[c4+3][r]=w.w;
    }
    __syncthreads();

    const int tx = tid & 15, ty = tid >> 4;
    float acc[4][4];
    #pragma unroll
    for (int i = 0; i < 4; i++)
        #pragma unroll
        for (int j = 0; j < 4; j++) acc[i][j] = 0.f;

    #pragma unroll 4
    for (int k = 0; k < 64; k++) {
        float ar[4], br[4];
        #pragma unroll
        for (int i = 0; i < 4; i++) ar[i] = Qs[k][ty*4 + i];
        #pragma unroll
        for (int j = 0; j < 4; j++) br[j] = Ks[k][tx*4 + j];
        #pragma unroll
        for (int i = 0; i < 4; i++)
            #pragma unroll
            for (int j = 0; j < 4; j++)
                acc[i][j] = fmaf(ar[i], br[j], acc[i][j]);
    }
    #pragma unroll
    for (int i = 0; i < 4; i++)
        #pragma unroll
        for (int j = 0; j < 4; j++)
            sb[(size_t)(qt + ty*4 + i) * SEQ + kt + tx*4 + j] = acc[i][j] * SCALE_;
}

// ---------------- row softmax over S (SEQ cols) -------------------------------
__global__ __launch_bounds__(256) void softmax_k()
{
    __shared__ float red[16];
    float* p = g_s + (size_t)blockIdx.x * SEQ;
    const int t = threadIdx.x;
    float4 v = ((float4*)p)[t];
    float m = fmaxf(fmaxf(v.x, v.y), fmaxf(v.z, v.w));
    #pragma unroll
    for (int o = 16; o > 0; o >>= 1) m = fmaxf(m, __shfl_xor_sync(0xffffffffu, m, o));
    if ((t & 31) == 0) red[t >> 5] = m;
    __syncthreads();
    m = red[0];
    #pragma unroll
    for (int i = 1; i < 8; i++) m = fmaxf(m, red[i]);

    v.x = __expf(v.x - m); v.y = __expf(v.y - m);
    v.z = __expf(v.z - m); v.w = __expf(v.w - m);
    float s = v.x + v.y + v.z + v.w;
    #pragma unroll
    for (int o = 16; o > 0; o >>= 1) s += __shfl_xor_sync(0xffffffffu, s, o);
    if ((t & 31) == 0) red[8 + (t >> 5)] = s;
    __syncthreads();
    s = red[8];
    #pragma unroll
    for (int i = 1; i < 8; i++) s += red[8 + i];
    const float inv = 1.f / s;
    v.x *= inv; v.y *= inv; v.z *= inv; v.w *= inv;
    ((float4*)p)[t] = v;
}

// ---------------- O = P @ V, writes merged-head layout ------------------------
__global__ __launch_bounds__(256) void attn_av_k(
    const float* __restrict__ V, int ldv, float* __restrict__ O)
{
    const int bh = blockIdx.y, b = bh >> 4, h = bh & 15;
    const int nt = blockIdx.x * 64;
    const float* sb = g_s + (size_t)bh * SEQ * SEQ + (size_t)nt * SEQ;
    const float* vb = V + (size_t)(b*SEQ) * ldv + h*DH_;
    float* ob = O + (size_t)(b*SEQ + nt) * DIM_ + h*DH_;

    __shared__ float Ps[64][65];   // [m][n]
    __shared__ float Vs[64][65];   // [m][d]
    const int tid = threadIdx.x;
    const int tx = tid & 15, ty = tid >> 4;
    float acc[4][4];
    #pragma unroll
    for (int i = 0; i < 4; i++)
        #pragma unroll
        for (int j = 0; j < 4; j++) acc[i][j] = 0.f;

    for (int mt = 0; mt < SEQ; mt += 64) {
        for (int i = tid; i < 64*16; i += 256) {
            const int r = i >> 4, c4 = (i & 15) * 4;
            const float4 v = *(const float4*)(sb + (size_t)r*SEQ + mt + c4);
            Ps[c4+0][r]=v.x; Ps[c4+1][r]=v.y; Ps[c4+2][r]=v.z; Ps[c4+3][r]=v.w;
            const float4 w = *(const float4*)(vb + (size_t)(mt + r)*ldv + c4);
            Vs[r][c4+0]=w.x; Vs[r][c4+1]=w.y; Vs[r][c4+2]=w.z; Vs[r][c4+3]=w.w;
        }
        __syncthreads();
        #pragma unroll 4
        for (int m = 0; m < 64; m++) {
            float pr[4], vr[4];
            #pragma unroll
            for (int i = 0; i < 4; i++) pr[i] = Ps[m][ty*4 + i];
            #pragma unroll
            for (int j = 0; j < 4; j++) vr[j] = Vs[m][tx*4 + j];
            #pragma unroll
            for (int i = 0; i < 4; i++)
                #pragma unroll
                for (int j = 0; j < 4; j++)
                    acc[i][j] = fmaf(pr[i], vr[j], acc[i][j]);
        }
        __syncthreads();
    }
    #pragma unroll
    for (int i = 0; i < 4; i++)
        #pragma unroll
        for (int j = 0; j < 4; j++)
            ob[(size_t)(ty*4 + i) * DIM_ + tx*4 + j] = acc[i][j];
}

// ---------------- host launch --------------------------------------------------
extern "C" void kernel_launch(void* const* d_in, const int* in_sizes, int n_in,
                              void* d_out, int out_size)
{
    (void)in_sizes; (void)n_in; (void)out_size;
    const float* x_in  = (const float*)d_in[0];
    const float* ctx   = (const float*)d_in[1];
    const float* ln1_g = (const float*)d_in[2];
    const float* ln1_b = (const float*)d_in[3];
    const float* w_qkv = (const float*)d_in[4];
    const float* w_o1  = (const float*)d_in[5];
    const float* b_o1  = (const float*)d_in[6];
    const float* ln2_g = (const float*)d_in[7];
    const float* ln2_b = (const float*)d_in[8];
    const float* w_q   = (const float*)d_in[9];
    const float* w_k   = (const float*)d_in[10];
    const float* w_v   = (const float*)d_in[11];
    const float* w_o2  = (const float*)d_in[12];
    const float* b_o2  = (const float*)d_in[13];
    const float* ln3_g = (const float*)d_in[14];
    const float* ln3_b = (const float*)d_in[15];
    const float* w_ff1 = (const float*)d_in[16];
    const float* b_ff1 = (const float*)d_in[17];
    const float* w_ff2 = (const float*)d_in[18];
    const float* b_ff2 = (const float*)d_in[19];

    float* x = (float*)d_out;           // running residual stream lives in d_out

    float *h, *qkv, *q2, *k2, *v2, *o, *mlp, *s;
    cudaGetSymbolAddress((void**)&h,   g_h);
    cudaGetSymbolAddress((void**)&qkv, g_qkv);
    cudaGetSymbolAddress((void**)&q2,  g_q2);
    cudaGetSymbolAddress((void**)&k2,  g_k2);
    cudaGetSymbolAddress((void**)&v2,  g_v2);
    cudaGetSymbolAddress((void**)&o,   g_o);
    cudaGetSymbolAddress((void**)&mlp, g_mlp);
    cudaGetSymbolAddress((void**)&s,   g_s);

    cudaMemcpyAsync(x, x_in, (size_t)ROWS * DIM_ * sizeof(float),
                    cudaMemcpyDeviceToDevice, 0);

    const dim3 gProj(DIM_/128,  ROWS/128);     // (8,16)  N=1024
    const dim3 gQKV(3*DIM_/128, ROWS/128);     // (24,16) N=3072
    const dim3 gFF1(MLP_/128,   ROWS/128);     // (32,16) N=4096
    const dim3 gQK(16, 16, B_*HEADS_);         // 64x64 score tiles
    const dim3 gAV(16, B_*HEADS_);

    for (int l = 0; l < DEPTH_; l++) {
        const float* wqkv_l = w_qkv + (size_t)l * DIM_ * 3*DIM_;
        const float* wo1_l  = w_o1  + (size_t)l * DIM_ * DIM_;
        const float* wq_l   = w_q   + (size_t)l * DIM_ * DIM_;
        const float* wk_l   = w_k   + (size_t)l * DIM_ * DIM_;
        const float* wv_l   = w_v   + (size_t)l * DIM_ * DIM_;
        const float* wo2_l  = w_o2  + (size_t)l * DIM_ * DIM_;
        const float* wff1_l = w_ff1 + (size_t)l * DIM_ * MLP_;
        const float* wff2_l = w_ff2 + (size_t)l * MLP_ * DIM_;

        // --- self attention ---
        layernorm_k<<<ROWS, 256>>>(x, ln1_g + l*DIM_, ln1_b + l*DIM_, h);
        sgemm_k<<<gQKV, 256>>>(h, wqkv_l, nullptr, nullptr, qkv,
                               ROWS, 3*DIM_, DIM_, 0);
        attn_qk_k<<<gQK, 256>>>(qkv, 3*DIM_, qkv + DIM_, 3*DIM_, s);
        softmax_k<<<B_*HEADS_*SEQ, 256>>>();
        attn_av_k<<<gAV, 256>>>(qkv + 2*DIM_, 3*DIM_, o);
        sgemm_k<<<gProj, 256>>>(o, wo1_l, b_o1 + l*DIM_, x, x,
                                ROWS, DIM_, DIM_, 0);

        // --- cross attention ---
        layernorm_k<<<ROWS, 256>>>(x, ln2_g + l*DIM_, ln2_b + l*DIM_, h);
        sgemm_k<<<gProj, 256>>>(h,   wq_l, nullptr, nullptr, q2, ROWS, DIM_, DIM_, 0);
        sgemm_k<<<gProj, 256>>>(ctx, wk_l, nullptr, nullptr, k2, ROWS, DIM_, DIM_, 0);
        sgemm_k<<<gProj, 256>>>(ctx, wv_l, nullptr, nullptr, v2, ROWS, DIM_, DIM_, 0);
        attn_qk_k<<<gQK, 256>>>(q2, DIM_, k2, DIM_, s);
        softmax_k<<<B_*HEADS_*SEQ, 256>>>();
        attn_av_k<<<gAV, 256>>>(v2, DIM_, o);
        sgemm_k<<<gProj, 256>>>(o, wo2_l, b_o2 + l*DIM_, x, x,
                                ROWS, DIM_, DIM_, 0);

        // --- FFN ---
        layernorm_k<<<ROWS, 256>>>(x, ln3_g + l*DIM_, ln3_b + l*DIM_, h);
        sgemm_k<<<gFF1, 256>>>(h, wff1_l, b_ff1 + l*MLP_, nullptr, mlp,
                               ROWS, MLP_, DIM_, 1);
        sgemm_k<<<gProj, 256>>>(mlp, wff2_l, b_ff2 + l*DIM_, x, x,
                                ROWS, DIM_, MLP_, 0);
    }
}

// round 2
// speedup vs baseline: 1.0505x; 1.0505x over previous
#include <cuda_runtime.h>
#include <math.h>

#define B_      2
#define SEQ     1024
#define DIM_    1024
#define HEADS_  16
#define DH_     64
#define MLP_    4096
#define ROWS    (B_*SEQ)          // 2048
#define SCALE_  0.125f            // 64^-0.5
#define DEPTH_  2

// ---------------- scratch (device globals: allocation-guard-safe) -------------
__device__ float g_h   [ROWS*DIM_];        // 8 MB
__device__ float g_qkv [ROWS*3*DIM_];      // 24 MB
__device__ float g_q2  [ROWS*DIM_];
__device__ float g_k2  [ROWS*DIM_];
__device__ float g_v2  [ROWS*DIM_];
__device__ float g_o   [ROWS*DIM_];
__device__ float g_mlp [ROWS*MLP_];        // 32 MB
__device__ float g_s   [B_*HEADS_*SEQ*SEQ];// 128 MB scores

// ---------------- layernorm: one block per row ------------------------------
__global__ __launch_bounds__(256) void layernorm_k(
    const float* __restrict__ x, const float* __restrict__ g,
    const float* __restrict__ b, float* __restrict__ out)
{
    __shared__ float red[18];
    const int row = blockIdx.x;
    const int t   = threadIdx.x;
    const float4 v = ((const float4*)(x + (size_t)row*DIM_))[t];
    float s  = v.x + v.y + v.z + v.w;
    float sq = v.x*v.x + v.y*v.y + v.z*v.z + v.w*v.w;
    #pragma unroll
    for (int o = 16; o > 0; o >>= 1) {
        s  += __shfl_down_sync(0xffffffffu, s,  o);
        sq += __shfl_down_sync(0xffffffffu, sq, o);
    }
    if ((t & 31) == 0) { red[t >> 5] = s; red[8 + (t >> 5)] = sq; }
    __syncthreads();
    if (t < 32) {
        float a = (t < 8) ? red[t]     : 0.f;
        float c = (t < 8) ? red[8 + t] : 0.f;
        #pragma unroll
        for (int o = 4; o > 0; o >>= 1) {
            a += __shfl_down_sync(0xffffffffu, a, o);
            c += __shfl_down_sync(0xffffffffu, c, o);
        }
        if (t == 0) { red[16] = a; red[17] = c; }
    }
    __syncthreads();
    const float mu   = red[16] * (1.f / DIM_);
    const float var  = red[17] * (1.f / DIM_) - mu * mu;
    const float rstd = rsqrtf(var + 1e-5f);
    const float4 gv = ((const float4*)g)[t];
    const float4 bv = ((const float4*)b)[t];
    float4 o4;
    o4.x = (v.x - mu) * rstd * gv.x + bv.x;
    o4.y = (v.y - mu) * rstd * gv.y + bv.y;
    o4.z = (v.z - mu) * rstd * gv.z + bv.z;
    o4.w = (v.w - mu) * rstd * gv.w + bv.w;
    ((float4*)(out + (size_t)row*DIM_))[t] = o4;
}

// ---------------- SGEMM 128x128x8, 256 thr, 8x8 micro-tile -------------------
// C[M,N] = act(A[M,K] @ B[K,N] + bias) + res.   All dims % (128,128,8) == 0.
// act: 0 = none, 1 = exact GELU (x * Phi(x)).
__global__ __launch_bounds__(256) void sgemm_k(
    const float* __restrict__ A, const float* __restrict__ B,
    const float* __restrict__ bias, const float* __restrict__ res,
    float* __restrict__ C, int M, int N, int K, int act)
{
    __shared__ float As[8][128];
    __shared__ float Bs[8][128];
    const int tid = threadIdx.x;
    const int bm  = blockIdx.y, bn = blockIdx.x;
    const int tx  = tid & 15, ty = tid >> 4;

    const int a_row = tid >> 1;          // 0..127
    const int a_col = (tid & 1) * 4;     // 0 or 4
    const int b_row = tid >> 5;          // 0..7
    const int b_col = (tid & 31) * 4;    // 0..124
    const float* Ap = A + (size_t)(bm*128 + a_row) * K + a_col;
    const float* Bp = B + (size_t)b_row * N + bn*128 + b_col;

    float acc[8][8];
    #pragma unroll
    for (int i = 0; i < 8; i++)
        #pragma unroll
        for (int j = 0; j < 8; j++) acc[i][j] = 0.f;

    for (int kk = 0; kk < K; kk += 8) {
        const float4 av = *(const float4*)(Ap + kk);
        As[a_col + 0][a_row] = av.x;
        As[a_col + 1][a_row] = av.y;
        As[a_col + 2][a_row] = av.z;
        As[a_col + 3][a_row] = av.w;
        *(float4*)&Bs[b_row][b_col] = *(const float4*)(Bp + (size_t)kk * N);
        __syncthreads();
        #pragma unroll
        for (int k = 0; k < 8; k++) {
            float ar[8], br[8];
            const float4 a0 = *(const float4*)&As[k][ty*8];
            const float4 a1 = *(const float4*)&As[k][ty*8 + 4];
            ar[0]=a0.x; ar[1]=a0.y; ar[2]=a0.z; ar[3]=a0.w;
            ar[4]=a1.x; ar[5]=a1.y; ar[6]=a1.z; ar[7]=a1.w;
            const float4 b0 = *(const float4*)&Bs[k][tx*8];
            const float4 b1 = *(const float4*)&Bs[k][tx*8 + 4];
            br[0]=b0.x; br[1]=b0.y; br[2]=b0.z; br[3]=b0.w;
            br[4]=b1.x; br[5]=b1.y; br[6]=b1.z; br[7]=b1.w;
            #pragma unroll
            for (int i = 0; i < 8; i++)
                #pragma unroll
                for (int j = 0; j < 8; j++)
                    acc[i][j] = fmaf(ar[i], br[j], acc[i][j]);
        }
        __syncthreads();
    }

    float bj[8];
    #pragma unroll
    for (int j = 0; j < 8; j++)
        bj[j] = bias ? bias[bn*128 + tx*8 + j] : 0.f;

    #pragma unroll
    for (int i = 0; i < 8; i++) {
        const size_t row = (size_t)(bm*128 + ty*8 + i);
        #pragma unroll
        for (int j = 0; j < 8; j++) {
            const size_t idx = row * N + bn*128 + tx*8 + j;
            float v = acc[i][j] + bj[j];
            if (act == 1) v = v * normcdff(v);     // exact GELU
            if (res) v += res[idx];
            C[idx] = v;
        }
    }
}

// ---------------- attention: S = scale * Q K^T (per batch-head) --------------
// Q rows stride ldq (head h at column offset h*DH_ already folded into base ptr math)
__global__ __launch_bounds__(256) void attn_qk_k(
    const float* __restrict__ Q, int ldq,
    const float* __restrict__ Kp, int ldk,
    float* __restrict__ S)
{
    const int bh = blockIdx.z, b = bh >> 4, h = bh & 15;
    const int qt = blockIdx.y * 64, kt = blockIdx.x * 64;
    const float* qb = Q  + (size_t)(b*SEQ + qt) * ldq + h*DH_;
    const float* kb = Kp + (size_t)(b*SEQ + kt) * ldk + h*DH_;
    float* sb = g_s + (size_t)bh * SEQ * SEQ;   // ignore S param; use global directly
    (void)S;

    __shared__ float Qs[64][65];   // [d][n]
    __shared__ float Ks[64][65];   // [d][m]
    const int tid = threadIdx.x;
    for (int i = tid; i < 64*16; i += 256) {
        const int r = i >> 4, c4 = (i & 15) * 4;
        const float4 v = *(const float4*)(qb + (size_t)r*ldq + c4);
        Qs[c4+0][r]=v.x; Qs[c4+1][r]=v.y; Qs[c4+2][r]=v.z; Qs[c4+3][r]=v.w;
        const float4 w = *(const float4*)(kb + (size_t)r*ldk + c4);
        Ks[c4+0][r]=w.x; Ks[c4+1][r]=w.y; Ks[c4+2][r]=w.z; Ks[c4+3][r]=w.w;
    }
    __syncthreads();

    const int tx = tid & 15, ty = tid >> 4;
    float acc[4][4];
    #pragma unroll
    for (int i = 0; i < 4; i++)
        #pragma unroll
        for (int j = 0; j < 4; j++) acc[i][j] = 0.f;

    #pragma unroll 4
    for (int k = 0; k < 64; k++) {
        float ar[4], br[4];
        #pragma unroll
        for (int i = 0; i < 4; i++) ar[i] = Qs[k][ty*4 + i];
        #pragma unroll
        for (int j = 0; j < 4; j++) br[j] = Ks[k][tx*4 + j];
        #pragma unroll
        for (int i = 0; i < 4; i++)
            #pragma unroll
            for (int j = 0; j < 4; j++)
                acc[i][j] = fmaf(ar[i], br[j], acc[i][j]);
    }
    #pragma unroll
    for (int i = 0; i < 4; i++)
        #pragma unroll
        for (int j = 0; j < 4; j++)
            sb[(size_t)(qt + ty*4 + i) * SEQ + kt + tx*4 + j] = acc[i][j] * SCALE_;
}

// ---------------- row softmax over S (SEQ cols) -------------------------------
__global__ __launch_bounds__(256) void softmax_k()
{
    __shared__ float red[16];
    float* p = g_s + (size_t)blockIdx.x * SEQ;
    const int t = threadIdx.x;
    float4 v = ((float4*)p)[t];
    float m = fmaxf(fmaxf(v.x, v.y), fmaxf(v.z, v.w));
    #pragma unroll
    for (int o = 16; o > 0; o >>= 1) m = fmaxf(m, __shfl_xor_sync(0xffffffffu, m, o));
    if ((t & 31) == 0) red[t >> 5] = m;
    __syncthreads();
    m = red[0];
    #pragma unroll
    for (int i = 1; i < 8; i++) m = fmaxf(m, red[i]);

    v.x = __expf(v.x - m); v.y = __expf(v.y - m);
    v.z = __expf(v.z - m); v.w = __expf(v.w - m);
    float s = v.x + v.y + v.z + v.w;
    #pragma unroll
    for (int o = 16; o > 0; o >>= 1) s += __shfl_xor_sync(0xffffffffu, s, o);
    if ((t & 31) == 0) red[8 + (t >> 5)] = s;
    __syncthreads();
    s = red[8];
    #pragma unroll
    for (int i = 1; i < 8; i++) s += red[8 + i];
    const float inv = 1.f / s;
    v.x *= inv; v.y *= inv; v.z *= inv; v.w *= inv;
    ((float4*)p)[t] = v;
}

// ---------------- O = P @ V, writes merged-head layout ------------------------
__global__ __launch_bounds__(256) void attn_av_k(
    const float* __restrict__ V, int ldv, float* __restrict__ O)
{
    const int bh = blockIdx.y, b = bh >> 4, h = bh & 15;
    const int nt = blockIdx.x * 64;
    const float* sb = g_s + (size_t)bh * SEQ * SEQ + (size_t)nt * SEQ;
    const float* vb = V + (size_t)(b*SEQ) * ldv + h*DH_;
    float* ob = O + (size_t)(b*SEQ + nt) * DIM_ + h*DH_;

    __shared__ float Ps[64][65];   // [m][n]
    __shared__ float Vs[64][65];   // [m][d]
    const int tid = threadIdx.x;
    const int tx = tid & 15, ty = tid >> 4;
    float acc[4][4];
    #pragma unroll
    for (int i = 0; i < 4; i++)
        #pragma unroll
        for (int j = 0; j < 4; j++) acc[i][j] = 0.f;

    for (int mt = 0; mt < SEQ; mt += 64) {
        for (int i = tid; i < 64*16; i += 256) {
            const int r = i >> 4, c4 = (i & 15) * 4;
            const float4 v = *(const float4*)(sb + (size_t)r*SEQ + mt + c4);
            Ps[c4+0][r]=v.x; Ps[c4+1][r]=v.y; Ps[c4+2][r]=v.z; Ps[c4+3][r]=v.w;
            const float4 w = *(const float4*)(vb + (size_t)(mt + r)*ldv + c4);
            Vs[r][c4+0]=w.x; Vs[r][c4+1]=w.y; Vs[r][c4+2]=w.z; Vs[r][c4+3]=w.w;
        }
        __syncthreads();
        #pragma unroll 4
        for (int m = 0; m < 64; m++) {
            float pr[4], vr[4];
            #pragma unroll
            for (int i = 0; i < 4; i++) pr[i] = Ps[m][ty*4 + i];
            #pragma unroll
            for (int j = 0; j < 4; j++) vr[j] = Vs[m][tx*4 + j];
            #pragma unroll
            for (int i = 0; i < 4; i++)
                #pragma unroll
                for (int j = 0; j < 4; j++)
                    acc[i][j] = fmaf(pr[i], vr[j], acc[i][j]);
        }
        __syncthreads();
    }
    #pragma unroll
    for (int i = 0; i < 4; i++)
        #pragma unroll
        for (int j = 0; j < 4; j++)
            ob[(size_t)(ty*4 + i) * DIM_ + tx*4 + j] = acc[i][j];
}

// ---------------- host launch --------------------------------------------------
extern "C" void kernel_launch(void* const* d_in, const int* in_sizes, int n_in,
                              void* d_out, int out_size)
{
    (void)in_sizes; (void)n_in; (void)out_size;
    const float* x_in  = (const float*)d_in[0];
    const float* ctx   = (const float*)d_in[1];
    const float* ln1_g = (const float*)d_in[2];
    const float* ln1_b = (const float*)d_in[3];
    const float* w_qkv = (const float*)d_in[4];
    const float* w_o1  = (const float*)d_in[5];
    const float* b_o1  = (const float*)d_in[6];
    const float* ln2_g = (const float*)d_in[7];
    const float* ln2_b = (const float*)d_in[8];
    const float* w_q   = (const float*)d_in[9];
    const float* w_k   = (const float*)d_in[10];
    const float* w_v   = (const float*)d_in[11];
    const float* w_o2  = (const float*)d_in[12];
    const float* b_o2  = (const float*)d_in[13];
    const float* ln3_g = (const float*)d_in[14];
    const float* ln3_b = (const float*)d_in[15];
    const float* w_ff1 = (const float*)d_in[16];
    const float* b_ff1 = (const float*)d_in[17];
    const float* w_ff2 = (const float*)d_in[18];
    const float* b_ff2 = (const float*)d_in[19];

    float* x = (float*)d_out;           // running residual stream lives in d_out

    float *h, *qkv, *q2, *k2, *v2, *o, *mlp, *s;
    cudaGetSymbolAddress((void**)&h,   g_h);
    cudaGetSymbolAddress((void**)&qkv, g_qkv);
    cudaGetSymbolAddress((void**)&q2,  g_q2);
    cudaGetSymbolAddress((void**)&k2,  g_k2);
    cudaGetSymbolAddress((void**)&v2,  g_v2);
    cudaGetSymbolAddress((void**)&o,   g_o);
    cudaGetSymbolAddress((void**)&mlp, g_mlp);
    cudaGetSymbolAddress((void**)&s,   g_s);

    cudaMemcpyAsync(x, x_in, (size_t)ROWS * DIM_ * sizeof(float),
                    cudaMemcpyDeviceToDevice, 0);

    const dim3 gProj(DIM_/128,  ROWS/128);     // (8,16)  N=1024
    const dim3 gQKV(3*DIM_/128, ROWS/128);     // (24,16) N=3072
    const dim3 gFF1(MLP_/128,   ROWS/128);     // (32,16) N=4096
    const dim3 gQK(16, 16, B_*HEADS_);         // 64x64 score tiles
    const dim3 gAV(16, B_*HEADS_);

    for (int l = 0; l < DEPTH_; l++) {
        const float* wqkv_l = w_qkv + (size_t)l * DIM_ * 3*DIM_;
        const float* wo1_l  = w_o1  + (size_t)l * DIM_ * DIM_;
        const float* wq_l   = w_q   + (size_t)l * DIM_ * DIM_;
        const float* wk_l   = w_k   + (size_t)l * DIM_ * DIM_;
        const float* wv_l   = w_v   + (size_t)l * DIM_ * DIM_;
        const float* wo2_l  = w_o2  + (size_t)l * DIM_ * DIM_;
        const float* wff1_l = w_ff1 + (size_t)l * DIM_ * MLP_;
        const float* wff2_l = w_ff2 + (size_t)l * MLP_ * DIM_;

        // --- self attention ---
        layernorm_k<<<ROWS, 256>>>(x, ln1_g + l*DIM_, ln1_b + l*DIM_, h);
        sgemm_k<<<gQKV, 256>>>(h, wqkv_l, nullptr, nullptr, qkv,
                               ROWS, 3*DIM_, DIM_, 0);
        attn_qk_k<<<gQK, 256>>>(qkv, 3*DIM_, qkv + DIM_, 3*DIM_, s);
        softmax_k<<<B_*HEADS_*SEQ, 256>>>();
        attn_av_k<<<gAV, 256>>>(qkv + 2*DIM_, 3*DIM_, o);
        sgemm_k<<<gProj, 256>>>(o, wo1_l, b_o1 + l*DIM_, x, x,
                                ROWS, DIM_, DIM_, 0);

        // --- cross attention ---
        layernorm_k<<<ROWS, 256>>>(x, ln2_g + l*DIM_, ln2_b + l*DIM_, h);
        sgemm_k<<<gProj, 256>>>(h,   wq_l, nullptr, nullptr, q2, ROWS, DIM_, DIM_, 0);
        sgemm_k<<<gProj, 256>>>(ctx, wk_l, nullptr, nullptr, k2, ROWS, DIM_, DIM_, 0);
        sgemm_k<<<gProj, 256>>>(ctx, wv_l, nullptr, nullptr, v2, ROWS, DIM_, DIM_, 0);
        attn_qk_k<<<gQK, 256>>>(q2, DIM_, k2, DIM_, s);
        softmax_k<<<B_*HEADS_*SEQ, 256>>>();
        attn_av_k<<<gAV, 256>>>(v2, DIM_, o);
        sgemm_k<<<gProj, 256>>>(o, wo2_l, b_o2 + l*DIM_, x, x,
                                ROWS, DIM_, DIM_, 0);

        // --- FFN ---
        layernorm_k<<<ROWS, 256>>>(x, ln3_g + l*DIM_, ln3_b + l*DIM_, h);
        sgemm_k<<<gFF1, 256>>>(h, wff1_l, b_ff1 + l*MLP_, nullptr, mlp,
                               ROWS, MLP_, DIM_, 1);
        sgemm_k<<<gProj, 256>>>(mlp, wff2_l, b_ff2 + l*DIM_, x, x,
                                ROWS, DIM_, MLP_, 0);
    }
}